// round 1
// baseline (speedup 1.0000x reference)
#include <cuda_runtime.h>

// SE module, quantized: x[64,1024,28,28] fp32, W1[256,1024], b1[256], W2[1024,256], b2[1024]
// out = x * hardsigmoid(qlinear2(relu(qlinear1(fq(mean_hw(fq(x)))))))

#define BB 64
#define CC 1024
#define HWW 784
#define RR 256
#define N_TOT (BB*CC*HWW)      // 51,380,224
#define N4 (N_TOT/4)           // 12,845,056
#define ROW4 (HWW/4)           // 196

// ---------------- scratch (no allocations allowed) ----------------
__device__ float g_pool[BB*CC];   // per-(b,c) integer sums of round(x/s)
__device__ float g_a[BB*CC];      // dequantized activation into fc1
__device__ float g_h[BB*RR];      // relu(fc1) output
__device__ float g_se[BB*CC];     // final gate
__device__ unsigned int g_amax_x;
__device__ unsigned int g_amax_w1;
__device__ unsigned int g_amax_w2;
__device__ unsigned int g_amax_h;

__device__ __forceinline__ float warpMaxf(float v) {
    #pragma unroll
    for (int o = 16; o; o >>= 1) v = fmaxf(v, __shfl_xor_sync(0xffffffffu, v, o));
    return v;
}
__device__ __forceinline__ float warpSumf(float v) {
    #pragma unroll
    for (int o = 16; o; o >>= 1) v += __shfl_xor_sync(0xffffffffu, v, o);
    return v;
}
__device__ __forceinline__ float clamp127(float r) {
    return fminf(fmaxf(r, -127.0f), 127.0f);
}

__global__ void k_init() {
    g_amax_x = 0u; g_amax_w1 = 0u; g_amax_w2 = 0u; g_amax_h = 0u;
}

// Generic abs-max over float4 data -> atomicMax on selected scalar.
// Non-negative float bit patterns are monotone as uints.
__global__ void k_amax(const float4* __restrict__ p, int n4, int which) {
    float m = 0.0f;
    int stride = gridDim.x * blockDim.x;
    for (int i = blockIdx.x * blockDim.x + threadIdx.x; i < n4; i += stride) {
        float4 v = p[i];
        m = fmaxf(m, fmaxf(fmaxf(fabsf(v.x), fabsf(v.y)),
                           fmaxf(fabsf(v.z), fabsf(v.w))));
    }
    m = warpMaxf(m);
    __shared__ float sm[32];
    int lane = threadIdx.x & 31, wid = threadIdx.x >> 5;
    int nw = blockDim.x >> 5;
    if (lane == 0) sm[wid] = m;
    __syncthreads();
    if (wid == 0) {
        float v = (lane < nw) ? sm[lane] : 0.0f;
        v = warpMaxf(v);
        if (lane == 0) {
            unsigned int* tgt = (which == 0) ? &g_amax_x
                              : (which == 1) ? &g_amax_w1 : &g_amax_w2;
            atomicMax(tgt, __float_as_uint(v));
        }
    }
}

// One warp per (b,c) row: sum of round(x/s) clipped to [-127,127].
// The sum is an exact fp32 integer (<= 127*784 << 2^24) -> deterministic.
__global__ void k_pool(const float4* __restrict__ x) {
    int gw = (blockIdx.x * blockDim.x + threadIdx.x) >> 5;
    int lane = threadIdx.x & 31;
    if (gw >= BB * CC) return;
    float s = fmaxf(__uint_as_float(g_amax_x) * (1.0f / 127.0f), 1e-8f);
    float inv_s = 1.0f / s;
    const float4* row = x + (size_t)gw * ROW4;
    float acc = 0.0f;
    for (int i = lane; i < ROW4; i += 32) {
        float4 v = row[i];
        acc += clamp127(rintf(v.x * inv_s));
        acc += clamp127(rintf(v.y * inv_s));
        acc += clamp127(rintf(v.z * inv_s));
        acc += clamp127(rintf(v.w * inv_s));
    }
    acc = warpSumf(acc);
    if (lane == 0) g_pool[gw] = acc;
}

// Single block: mean -> fq -> fq (the qlinear's input quantization), writes g_a.
__global__ void k_mlp_in() {
    __shared__ float red[32];
    __shared__ float s_scale2, s_scalea;
    int tid = threadIdx.x, lane = tid & 31, wid = tid >> 5;
    float s = fmaxf(__uint_as_float(g_amax_x) * (1.0f / 127.0f), 1e-8f);
    float ms = s / 784.0f;   // m_i = sum_i * ms

    // phase 1: amax |m|
    float m = 0.0f;
    for (int i = tid; i < BB * CC; i += 1024) m = fmaxf(m, fabsf(g_pool[i] * ms));
    m = warpMaxf(m);
    if (lane == 0) red[wid] = m;
    __syncthreads();
    if (wid == 0) {
        float v = red[lane];
        v = warpMaxf(v);
        if (lane == 0) s_scale2 = fmaxf(v * (1.0f / 127.0f), 1e-8f);
    }
    __syncthreads();
    float scale2 = s_scale2;

    // phase 2: amax |fq(m)|
    float ma = 0.0f;
    for (int i = tid; i < BB * CC; i += 1024) {
        float mi = g_pool[i] * ms;
        float q = clamp127(rintf(mi / scale2)) * scale2;
        ma = fmaxf(ma, fabsf(q));
    }
    ma = warpMaxf(ma);
    __syncthreads();
    if (lane == 0) red[wid] = ma;
    __syncthreads();
    if (wid == 0) {
        float v = red[lane];
        v = warpMaxf(v);
        if (lane == 0) s_scalea = fmaxf(v * (1.0f / 127.0f), 1e-8f);
    }
    __syncthreads();
    float sa = s_scalea;

    // phase 3: a = fq(fq(m))
    for (int i = tid; i < BB * CC; i += 1024) {
        float mi = g_pool[i] * ms;
        float q = clamp127(rintf(mi / scale2)) * scale2;
        g_a[i] = clamp127(rintf(q / sa)) * sa;
    }
}

// fc1: one warp per (b,r) output, dot over C=1024. relu + block amax epilogue.
__global__ void k_fc1(const float* __restrict__ W1, const float* __restrict__ b1) {
    int gw = (blockIdx.x * blockDim.x + threadIdx.x) >> 5;   // 0..16383
    int lane = threadIdx.x & 31;
    int b = gw >> 8;          // /256
    int r = gw & 255;
    float sw = fmaxf(__uint_as_float(g_amax_w1) * (1.0f / 127.0f), 1e-8f);
    const float* arow = g_a + b * CC;
    const float* wrow = W1 + r * CC;
    float acc = 0.0f;
    #pragma unroll 4
    for (int k = lane; k < CC; k += 32) {
        float wq = clamp127(rintf(wrow[k] / sw)) * sw;
        acc += arow[k] * wq;
    }
    acc = warpSumf(acc);
    float y = 0.0f;
    __shared__ float sm[8];
    if (lane == 0) {
        y = fmaxf(acc + b1[r], 0.0f);
        g_h[gw] = y;
        sm[threadIdx.x >> 5] = y;   // relu output >= 0, amax == max
    }
    __syncthreads();
    if (threadIdx.x == 0) {
        float mx = sm[0];
        #pragma unroll
        for (int i = 1; i < 8; i++) mx = fmaxf(mx, sm[i]);
        atomicMax(&g_amax_h, __float_as_uint(mx));
    }
}

// fc2: one warp per (b,c) output, dot over R=256; hardsigmoid -> g_se.
__global__ void k_fc2(const float* __restrict__ W2, const float* __restrict__ b2) {
    int gw = (blockIdx.x * blockDim.x + threadIdx.x) >> 5;   // 0..65535
    int lane = threadIdx.x & 31;
    int b = gw >> 10;
    int c = gw & 1023;
    float sh = fmaxf(__uint_as_float(g_amax_h) * (1.0f / 127.0f), 1e-8f);
    float sw = fmaxf(__uint_as_float(g_amax_w2) * (1.0f / 127.0f), 1e-8f);
    const float* hrow = g_h + b * RR;
    const float* wrow = W2 + c * RR;
    float acc = 0.0f;
    #pragma unroll
    for (int k = lane; k < RR; k += 32) {
        float hq = clamp127(rintf(hrow[k] / sh)) * sh;
        float wq = clamp127(rintf(wrow[k] / sw)) * sw;
        acc += hq * wq;
    }
    acc = warpSumf(acc);
    if (lane == 0) {
        float t = acc + b2[c];
        g_se[gw] = fminf(fmaxf(t / 6.0f + 0.5f, 0.0f), 1.0f);
    }
}

// out = x * gate[b,c]   (original fp32 x, not quantized)
__global__ void k_scale(const float4* __restrict__ x, float4* __restrict__ out) {
    int stride = gridDim.x * blockDim.x;
    for (int i = blockIdx.x * blockDim.x + threadIdx.x; i < N4; i += stride) {
        int row = i / ROW4;                 // constant divisor -> mul/shift
        float g = g_se[row];
        float4 v = x[i];
        v.x *= g; v.y *= g; v.z *= g; v.w *= g;
        out[i] = v;
    }
}

extern "C" void kernel_launch(void* const* d_in, const int* in_sizes, int n_in,
                              void* d_out, int out_size) {
    (void)in_sizes; (void)n_in; (void)out_size;
    const float* x  = (const float*)d_in[0];
    const float* W1 = (const float*)d_in[1];
    const float* b1 = (const float*)d_in[2];
    const float* W2 = (const float*)d_in[3];
    const float* b2 = (const float*)d_in[4];
    float* out = (float*)d_out;

    k_init<<<1, 32>>>();
    k_amax<<<4096, 256>>>((const float4*)x, N4, 0);                 // amax |x|
    k_amax<<<256, 256>>>((const float4*)W1, (RR * CC) / 4, 1);      // amax |W1|
    k_amax<<<256, 256>>>((const float4*)W2, (CC * RR) / 4, 2);      // amax |W2|
    k_pool<<<(BB * CC) / 8, 256>>>((const float4*)x);               // 8 warps/block
    k_mlp_in<<<1, 1024>>>();
    k_fc1<<<(BB * RR) / 8, 256>>>(W1, b1);
    k_fc2<<<(BB * CC) / 8, 256>>>(W2, b2);
    k_scale<<<8192, 256>>>((const float4*)x, (float4*)out);
}

// round 2
// speedup vs baseline: 1.3425x; 1.3425x over previous
#include <cuda_runtime.h>

// SE module, quantized: x[64,1024,28,28] fp32, W1[256,1024], b1[256], W2[1024,256], b2[1024]
// out = x * hardsigmoid(qlinear2(relu(qlinear1(fq(mean_hw(fq(x)))))))

#define BB 64
#define CC 1024
#define HWW 784
#define RR 256
#define N_TOT (BB*CC*HWW)      // 51,380,224
#define N4 (N_TOT/4)           // 12,845,056
#define ROW4 (HWW/4)           // 196
#define NROWS (BB*CC)          // 65536

#define PERSIST_BLOCKS 1184    // 148 SMs * 8 blocks (256 thr) = single wave
#define MLP_BLOCKS 64

// ---------------- scratch (no allocations allowed) ----------------
__device__ float g_pool[NROWS];   // per-(b,c) integer sums of round(x/s)
__device__ float g_se[NROWS];     // final gate
__device__ unsigned int g_amax_x, g_amax_w1, g_amax_w2;
__device__ unsigned int g_amax_m, g_amax_a, g_amax_h;
__device__ volatile unsigned int g_bar_cnt[4];
__device__ volatile unsigned int g_bar_gen[4];

__device__ __forceinline__ float warpMaxf(float v) {
    #pragma unroll
    for (int o = 16; o; o >>= 1) v = fmaxf(v, __shfl_xor_sync(0xffffffffu, v, o));
    return v;
}
__device__ __forceinline__ float warpSumf(float v) {
    #pragma unroll
    for (int o = 16; o; o >>= 1) v += __shfl_xor_sync(0xffffffffu, v, o);
    return v;
}
__device__ __forceinline__ float clamp127(float r) {
    return fminf(fmaxf(r, -127.0f), 127.0f);
}
__device__ __forceinline__ float sc_of(unsigned int bits) {
    return fmaxf(__uint_as_float(bits) * (1.0f / 127.0f), 1e-8f);
}

// Generation-counter grid barrier. cnt self-resets to 0; gen grows
// monotonically (replay-safe: comparisons are relative).
__device__ __forceinline__ void grid_barrier(int k, unsigned int nblocks) {
    __syncthreads();
    if (threadIdx.x == 0) {
        __threadfence();
        unsigned int g = g_bar_gen[k];
        unsigned int a = atomicAdd((unsigned int*)&g_bar_cnt[k], 1u);
        if (a == nblocks - 1u) {
            g_bar_cnt[k] = 0u;
            __threadfence();
            atomicAdd((unsigned int*)&g_bar_gen[k], 1u);
        } else {
            while (g_bar_gen[k] == g) { }
        }
        __threadfence();
    }
    __syncthreads();
}

__global__ void k_init() {
    g_amax_x = 0u; g_amax_w1 = 0u; g_amax_w2 = 0u;
    g_amax_m = 0u; g_amax_a = 0u; g_amax_h = 0u;
}

// One launch: blocks [0,128) -> amax W1, [128,256) -> amax W2,
// [256, 256+PERSIST_BLOCKS) -> amax x (single-wave, forward walk so the
// TAIL of x is L2-resident on exit).
__global__ void k_amax_all(const float4* __restrict__ x,
                           const float4* __restrict__ w1,
                           const float4* __restrict__ w2) {
    const float4* p; int n4; unsigned int* tgt; int base, nth;
    if (blockIdx.x < 128) {
        p = w1; n4 = (RR*CC)/4; tgt = &g_amax_w1;
        base = blockIdx.x * blockDim.x + threadIdx.x; nth = 128 * blockDim.x;
    } else if (blockIdx.x < 256) {
        p = w2; n4 = (CC*RR)/4; tgt = &g_amax_w2;
        base = (blockIdx.x - 128) * blockDim.x + threadIdx.x; nth = 128 * blockDim.x;
    } else {
        p = x; n4 = N4; tgt = &g_amax_x;
        base = (blockIdx.x - 256) * blockDim.x + threadIdx.x;
        nth = PERSIST_BLOCKS * blockDim.x;
    }
    float m = 0.0f;
    for (int i = base; i < n4; i += nth) {
        float4 v = p[i];
        m = fmaxf(m, fmaxf(fmaxf(fabsf(v.x), fabsf(v.y)),
                           fmaxf(fabsf(v.z), fabsf(v.w))));
    }
    m = warpMaxf(m);
    __shared__ float sm[8];
    int lane = threadIdx.x & 31, wid = threadIdx.x >> 5;
    if (lane == 0) sm[wid] = m;
    __syncthreads();
    if (threadIdx.x == 0) {
        float v = sm[0];
        #pragma unroll
        for (int i = 1; i < 8; i++) v = fmaxf(v, sm[i]);
        atomicMax(tgt, __float_as_uint(v));
    }
}

// One warp per (b,c) row, processed in REVERSE address order so we start on
// the tail of x that k_amax_all left in L2. Sum of round(x/s) clipped to
// [-127,127] is an exact fp32 integer -> deterministic.
__global__ void k_pool(const float4* __restrict__ x) {
    int gw = (blockIdx.x * blockDim.x + threadIdx.x) >> 5;
    int lane = threadIdx.x & 31;
    if (gw >= NROWS) return;
    int row = (NROWS - 1) - gw;                     // reverse temporal order
    float inv_s = 1.0f / sc_of(g_amax_x);
    const float4* rp = x + (size_t)row * ROW4;
    float acc = 0.0f;
    for (int i = lane; i < ROW4; i += 32) {
        float4 v = rp[i];
        acc += clamp127(rintf(v.x * inv_s));
        acc += clamp127(rintf(v.y * inv_s));
        acc += clamp127(rintf(v.z * inv_s));
        acc += clamp127(rintf(v.w * inv_s));
    }
    acc = warpSumf(acc);
    if (lane == 0) g_pool[row] = acc;
}

// Fused MLP: mean->fq->fq, fc1+relu, amax_h, fc2+hardsigmoid -> g_se.
// 64 blocks (one per batch) x 1024 threads; grid barriers between global
// amax stages. All activations stay in smem.
__global__ void __launch_bounds__(1024, 1) k_mlp(
        const float* __restrict__ W1, const float* __restrict__ b1,
        const float* __restrict__ W2, const float* __restrict__ b2) {
    __shared__ float a_sm[CC];
    __shared__ float h_sm[RR];
    __shared__ float red[32];
    int tid = threadIdx.x, lane = tid & 31, wid = tid >> 5;
    int b = blockIdx.x;

    float ms = sc_of(g_amax_x) / 784.0f;
    float m_val = g_pool[b * CC + tid] * ms;

    // stage 1: global amax |m|
    float mv = warpMaxf(fabsf(m_val));
    if (lane == 0) red[wid] = mv;
    __syncthreads();
    if (tid == 0) {
        float v = red[0];
        #pragma unroll
        for (int i = 1; i < 32; i++) v = fmaxf(v, red[i]);
        atomicMax(&g_amax_m, __float_as_uint(v));
    }
    grid_barrier(0, MLP_BLOCKS);

    // stage 2: q = fq(m); global amax |q|
    float scale2 = sc_of(g_amax_m);
    float q = clamp127(rintf(m_val / scale2)) * scale2;
    float qv = warpMaxf(fabsf(q));
    __syncthreads();
    if (lane == 0) red[wid] = qv;
    __syncthreads();
    if (tid == 0) {
        float v = red[0];
        #pragma unroll
        for (int i = 1; i < 32; i++) v = fmaxf(v, red[i]);
        atomicMax(&g_amax_a, __float_as_uint(v));
    }
    grid_barrier(1, MLP_BLOCKS);

    // stage 3: a = fq(q) into smem
    float sa = sc_of(g_amax_a);
    a_sm[tid] = clamp127(rintf(q / sa)) * sa;
    __syncthreads();

    // fc1: 32 warps x 8 outputs each, warp-cooperative dot over C=1024
    float inv_sw1 = 1.0f / sc_of(g_amax_w1);
    float sw1 = sc_of(g_amax_w1);
    float hmax = 0.0f;
    #pragma unroll
    for (int rr = 0; rr < 8; rr++) {
        int r = wid * 8 + rr;
        const float* wrow = W1 + r * CC;
        float acc = 0.0f;
        #pragma unroll 8
        for (int k = lane; k < CC; k += 32)
            acc += a_sm[k] * (clamp127(rintf(wrow[k] * inv_sw1)) * sw1);
        acc = warpSumf(acc);
        if (lane == 0) {
            float y = fmaxf(acc + b1[r], 0.0f);
            h_sm[r] = y;
            hmax = fmaxf(hmax, y);
        }
    }
    if (lane == 0) atomicMax(&g_amax_h, __float_as_uint(hmax));
    grid_barrier(2, MLP_BLOCKS);

    // fc2: 32 warps x 32 outputs each, dot over R=256 -> hardsigmoid
    float sh = sc_of(g_amax_h);
    float inv_sh = 1.0f / sh;
    float sw2 = sc_of(g_amax_w2);
    float inv_sw2 = 1.0f / sw2;
    #pragma unroll
    for (int cc = 0; cc < 32; cc++) {
        int c = wid * 32 + cc;
        const float* wrow = W2 + c * RR;
        float acc = 0.0f;
        #pragma unroll
        for (int k = lane; k < RR; k += 32) {
            float hq = clamp127(rintf(h_sm[k] * inv_sh)) * sh;
            float wq = clamp127(rintf(wrow[k] * inv_sw2)) * sw2;
            acc += hq * wq;
        }
        acc = warpSumf(acc);
        if (lane == 0) {
            float t = acc + b2[c];
            g_se[b * CC + c] = fminf(fmaxf(t / 6.0f + 0.5f, 0.0f), 1.0f);
        }
    }
}

// out = x * gate[b,c]. Forward single-wave walk (front of x is L2-resident
// after the reversed pool). Last use of x -> streaming loads/stores.
__global__ void k_scale(const float4* __restrict__ x, float4* __restrict__ out) {
    const int stride = PERSIST_BLOCKS * 256;
    for (int i = blockIdx.x * blockDim.x + threadIdx.x; i < N4; i += stride) {
        int row = i / ROW4;                 // constant divisor -> mul/shift
        float g = g_se[row];
        float4 v = __ldcs(x + i);
        v.x *= g; v.y *= g; v.z *= g; v.w *= g;
        __stcs(out + i, v);
    }
}

extern "C" void kernel_launch(void* const* d_in, const int* in_sizes, int n_in,
                              void* d_out, int out_size) {
    (void)in_sizes; (void)n_in; (void)out_size;
    const float* x  = (const float*)d_in[0];
    const float* W1 = (const float*)d_in[1];
    const float* b1 = (const float*)d_in[2];
    const float* W2 = (const float*)d_in[3];
    const float* b2 = (const float*)d_in[4];
    float* out = (float*)d_out;

    k_init<<<1, 32>>>();
    k_amax_all<<<256 + PERSIST_BLOCKS, 256>>>((const float4*)x,
                                              (const float4*)W1,
                                              (const float4*)W2);
    k_pool<<<NROWS / 8, 256>>>((const float4*)x);
    k_mlp<<<MLP_BLOCKS, 1024>>>(W1, b1, W2, b2);
    k_scale<<<PERSIST_BLOCKS, 256>>>((const float4*)x, (float4*)out);
}